// round 15
// baseline (speedup 1.0000x reference)
#include <cuda_runtime.h>
#include <cuda_fp16.h>
#include <math.h>
#include <stdint.h>

#define BATCH 4
#define NSEQ 2048
#define DIM 512
#define HEADS 8
#define DHEAD 64
#define BH (BATCH*HEADS)      /* 32  */
#define ROWS (BATCH*NSEQ)     /* 8192 */
#define NT64 32               /* 64-row k tiles */
#define NQT 16                /* 128-row q tiles */
#define MASK_FILL 1e-8f

// ---------------- scratch ----------------
__device__ float g_v  [BH * NSEQ * DHEAD];          // fp32 V (vsuf)
__device__ float g_vsuf[BH * (NT64 + 1) * DHEAD];
__device__ float g_vpart[BH * NT64 * DHEAD];        // per-tile column sums
// pre-split fp16 hi/lo word images of hn and W ([row][256 words])
__device__ uint32_t g_hnh[ROWS * 256];
__device__ uint32_t g_hnl[ROWS * 256];
__device__ uint32_t g_wh [1536 * 256];
__device__ uint32_t g_wl [1536 * 256];
// MMA-ready fp16 images for attention (36-word row stride / VP 72)
__device__ uint32_t g_qih[BH * NQT * 128 * 36];
__device__ uint32_t g_qil[BH * NQT * 128 * 36];
__device__ uint32_t g_kih[BH * NT64 * 64 * 36];
__device__ uint32_t g_kil[BH * NT64 * 64 * 36];
__device__ uint32_t g_vp [BH * NT64 * 32 * 72];

// ---------------- helpers ----------------
__device__ __forceinline__ void mma16(float* d, uint32_t a0, uint32_t a1,
                                      uint32_t a2, uint32_t a3,
                                      uint32_t b0, uint32_t b1) {
    asm volatile(
        "mma.sync.aligned.m16n8k16.row.col.f32.f16.f16.f32 "
        "{%0,%1,%2,%3}, {%4,%5,%6,%7}, {%8,%9}, {%0,%1,%2,%3};"
        : "+f"(d[0]), "+f"(d[1]), "+f"(d[2]), "+f"(d[3])
        : "r"(a0), "r"(a1), "r"(a2), "r"(a3), "r"(b0), "r"(b1));
}
__device__ __forceinline__ uint32_t h2u(__half2 h) {
    return *reinterpret_cast<uint32_t*>(&h);
}
__device__ __forceinline__ uint32_t pack2(float a, float b) {
    __half2 h = __floats2half2_rn(a, b);
    return h2u(h);
}
__device__ __forceinline__ void split2(float x, float y, uint32_t& hi, uint32_t& lo) {
    __half2 h = __floats2half2_rn(x, y);
    float2 back = __half22float2(h);
    hi = h2u(h);
    lo = pack2(x - back.x, y - back.y);
}
__device__ __forceinline__ uint32_t smem_u32(const void* p) {
    uint32_t a;
    asm("{ .reg .u64 t; cvta.to.shared.u64 t, %1; cvt.u32.u64 %0, t; }" : "=r"(a) : "l"(p));
    return a;
}
#define CPA16(dst, src) \
    asm volatile("cp.async.cg.shared.global [%0], [%1], 16;" :: "r"(dst), "l"(src) : "memory")
#define CP_COMMIT() asm volatile("cp.async.commit_group;" ::: "memory")
#define CP_WAIT0()  asm volatile("cp.async.wait_group 0;" ::: "memory")
#define CP_WAIT1()  asm volatile("cp.async.wait_group 1;" ::: "memory")

// ---------------- 0) no-op launch (ncu slot alignment: gemm -> 4th) -------
__global__ void noop_kernel() {}

// ---------------- 1) LayerNorm -> fp16 hi/lo word images ----------------
__global__ __launch_bounds__(128)
void ln_kernel(const float* __restrict__ x,
               const float* __restrict__ gamma,
               const float* __restrict__ beta) {
    int row = blockIdx.x;
    int tid = threadIdx.x;
    const float4* xr = (const float4*)(x + (size_t)row * DIM);
    float4 v = xr[tid];
    float s  = v.x + v.y + v.z + v.w;
    float s2 = v.x*v.x + v.y*v.y + v.z*v.z + v.w*v.w;
    #pragma unroll
    for (int o = 16; o > 0; o >>= 1) {
        s  += __shfl_xor_sync(0xffffffffu, s,  o);
        s2 += __shfl_xor_sync(0xffffffffu, s2, o);
    }
    __shared__ float ss[4], ss2[4];
    int w = tid >> 5;
    if ((tid & 31) == 0) { ss[w] = s; ss2[w] = s2; }
    __syncthreads();
    s  = ss[0] + ss[1] + ss[2] + ss[3];
    s2 = ss2[0] + ss2[1] + ss2[2] + ss2[3];
    float mean = s * (1.0f / DIM);
    float var  = s2 * (1.0f / DIM) - mean * mean;
    float inv  = rsqrtf(var + 1e-5f);
    float4 g  = ((const float4*)gamma)[tid];
    float4 bt = ((const float4*)beta)[tid];
    float ox = (v.x - mean) * inv * g.x + bt.x;
    float oy = (v.y - mean) * inv * g.y + bt.y;
    float oz = (v.z - mean) * inv * g.z + bt.z;
    float ow = (v.w - mean) * inv * g.w + bt.w;
    uint32_t h0, l0, h1, l1;
    split2(ox, oy, h0, l0); split2(oz, ow, h1, l1);
    size_t base = (size_t)row * 256 + 2 * tid;
    *(uint2*)&g_hnh[base] = make_uint2(h0, h1);
    *(uint2*)&g_hnl[base] = make_uint2(l0, l1);
}

// ---------------- 1b) W -> fp16 hi/lo word images ----------------
__global__ __launch_bounds__(128)
void wconv_kernel(const float* __restrict__ W) {
    int row = blockIdx.x;           // 0..1535
    int tid = threadIdx.x;          // 128 threads * 4 elems
    float4 v = *(const float4*)&W[(size_t)row * DIM + 4 * tid];
    uint32_t h0, l0, h1, l1;
    split2(v.x, v.y, h0, l0); split2(v.z, v.w, h1, l1);
    size_t base = (size_t)row * 256 + 2 * tid;
    *(uint2*)&g_wh[base] = make_uint2(h0, h1);
    *(uint2*)&g_wl[base] = make_uint2(l0, l1);
}

// ---------------- 2) QKV GEMM: pre-split images, 16 half-chunks, 3-stage --
// Stage (30720 B): AHI [128][20w] | ALO | BHI [64][20w] | BLO
// (20-word row stride: conflict-free frag loads, 16B-aligned cp.async rows)
#define GSTG 30720
#define GEMM_SMEM 92160
__global__ __launch_bounds__(256, 2)
void qkv_gemm() {
    extern __shared__ char smc[];
    const uint32_t sb = smem_u32(smc);
    const int nb = blockIdx.x * 64;
    const int mb = blockIdx.y * 128;
    const int tid = threadIdx.x;
    const int w = tid >> 5, lane = tid & 31;
    const int g = lane >> 2, q = lane & 3;
    const int mg = w & 3;          // m-group: rows 32*mg..+31
    const int ng = w >> 2;         // n-group: cols 32*ng..+31

    float C[2][4][4];
    #pragma unroll
    for (int mt = 0; mt < 2; mt++)
        #pragma unroll
        for (int n = 0; n < 4; n++)
            #pragma unroll
            for (int j = 0; j < 4; j++) C[mt][n][j] = 0.f;

    // prefetch chunk ch -> stage stg: 1536 x 16B (A hi/lo 128x64B, B hi/lo 64x64B)
    #define GP(ch, stg)                                                       \
    do {                                                                      \
        uint32_t dstb = sb + (stg) * GSTG;                                    \
        int kw = (ch) * 16;                                                   \
        _Pragma("unroll")                                                     \
        for (int i = 0; i < 6; i++) {                                         \
            int c = tid + i * 256;                                            \
            if (c < 512) {                                                    \
                int row = c >> 2, sg = c & 3;                                 \
                CPA16(dstb + row * 80 + sg * 16,                              \
                      &g_hnh[(size_t)(mb + row) * 256 + kw + sg * 4]);        \
            } else if (c < 1024) {                                            \
                int c2 = c - 512; int row = c2 >> 2, sg = c2 & 3;             \
                CPA16(dstb + 10240 + row * 80 + sg * 16,                      \
                      &g_hnl[(size_t)(mb + row) * 256 + kw + sg * 4]);        \
            } else if (c < 1280) {                                            \
                int c2 = c - 1024; int row = c2 >> 2, sg = c2 & 3;            \
                CPA16(dstb + 20480 + row * 80 + sg * 16,                      \
                      &g_wh[(size_t)(nb + row) * 256 + kw + sg * 4]);         \
            } else {                                                          \
                int c2 = c - 1280; int row = c2 >> 2, sg = c2 & 3;            \
                CPA16(dstb + 25600 + row * 80 + sg * 16,                      \
                      &g_wl[(size_t)(nb + row) * 256 + kw + sg * 4]);         \
            }                                                                 \
        }                                                                     \
    } while (0)

    GP(0, 0); CP_COMMIT();
    GP(1, 1); CP_COMMIT();

    for (int ch = 0; ch < 16; ch++) {
        CP_WAIT1();              // oldest outstanding group (chunk ch) done
        __syncthreads();
        if (ch + 2 < 16) GP(ch + 2, (ch + 2) % 3);
        CP_COMMIT();             // (empty group near tail keeps FIFO drain correct)

        const uint32_t* AH = (const uint32_t*)(smc + (ch % 3) * GSTG);
        const uint32_t* AL = AH + 2560;
        const uint32_t* BHp = AH + 5120;
        const uint32_t* BLp = AH + 6400;
        #pragma unroll
        for (int ksp = 0; ksp < 2; ksp++) {
            uint32_t ah[2][4], al[2][4];
            #pragma unroll
            for (int mt = 0; mt < 2; mt++) {
                int a0w = (32 * mg + 16 * mt + g) * 20 + 8 * ksp + q;
                int a1w = a0w + 8 * 20;
                ah[mt][0] = AH[a0w];     ah[mt][1] = AH[a1w];
                ah[mt][2] = AH[a0w + 4]; ah[mt][3] = AH[a1w + 4];
                al[mt][0] = AL[a0w];     al[mt][1] = AL[a1w];
                al[mt][2] = AL[a0w + 4]; al[mt][3] = AL[a1w + 4];
            }
            #pragma unroll
            for (int n = 0; n < 4; n++) {
                int bw = (32 * ng + 8 * n + g) * 20 + 8 * ksp + q;
                uint32_t bh0 = BHp[bw], bh1 = BHp[bw + 4];
                uint32_t bl0 = BLp[bw], bl1 = BLp[bw + 4];
                #pragma unroll
                for (int mt = 0; mt < 2; mt++) {
                    mma16(C[mt][n], ah[mt][0], ah[mt][1], ah[mt][2], ah[mt][3], bh0, bh1);
                    mma16(C[mt][n], ah[mt][0], ah[mt][1], ah[mt][2], ah[mt][3], bl0, bl1);
                    mma16(C[mt][n], al[mt][0], al[mt][1], al[mt][2], al[mt][3], bh0, bh1);
                }
            }
        }
    }

    // ---- epilogue: emit MMA-ready images (q,k) / fp32 + VP image (v) ----
    const int chunk = nb / 512;            // 0=q 1=k 2=v
    const int head  = (nb % 512) >> 6;
    if (chunk == 0) {
        #pragma unroll
        for (int mt = 0; mt < 2; mt++)
            #pragma unroll
            for (int n = 0; n < 4; n++) {
                int na = 4 * ng + n;
                #pragma unroll
                for (int rr = 0; rr < 2; rr++) {
                    int m  = mb + 32 * mg + 16 * mt + g + rr * 8;
                    int bi = m >> 11, nr = m & 2047;
                    int bhh = bi * HEADS + head;
                    size_t idx = ((size_t)(bhh * NQT + (nr >> 7)) * 128 + (nr & 127)) * 36 + 4 * na + q;
                    uint32_t hi, lo;
                    split2(C[mt][n][rr * 2], C[mt][n][rr * 2 + 1], hi, lo);
                    g_qih[idx] = hi; g_qil[idx] = lo;
                }
            }
    } else if (chunk == 1) {
        #pragma unroll
        for (int mt = 0; mt < 2; mt++)
            #pragma unroll
            for (int n = 0; n < 4; n++) {
                int na = 4 * ng + n;
                #pragma unroll
                for (int rr = 0; rr < 2; rr++) {
                    int m  = mb + 32 * mg + 16 * mt + g + rr * 8;
                    int bi = m >> 11, nr = m & 2047;
                    int bhh = bi * HEADS + head;
                    size_t idx = ((size_t)(bhh * NT64 + (nr >> 6)) * 64 + (nr & 63)) * 36 + 4 * na + q;
                    uint32_t hi, lo;
                    split2(C[mt][n][rr * 2], C[mt][n][rr * 2 + 1], hi, lo);
                    g_kih[idx] = hi; g_kil[idx] = lo;
                }
            }
    } else {
        // fp32 V for vsuf
        #pragma unroll
        for (int mt = 0; mt < 2; mt++)
            #pragma unroll
            for (int n = 0; n < 4; n++) {
                int col = 8 * (4 * ng + n) + 2 * q;
                #pragma unroll
                for (int rr = 0; rr < 2; rr++) {
                    int m  = mb + 32 * mg + 16 * mt + g + rr * 8;
                    int bi = m >> 11, nr = m & 2047;
                    size_t ob = (((size_t)(bi * HEADS + head)) * NSEQ + nr) * DHEAD + col;
                    *(float2*)&g_v[ob] = make_float2(C[mt][n][rr * 2], C[mt][n][rr * 2 + 1]);
                }
            }
        // VP image: half2 word [r2][d] = (V[2r2][d], V[2r2+1][d]); even-g lanes
        #pragma unroll
        for (int mt = 0; mt < 2; mt++)
            #pragma unroll
            for (int n = 0; n < 4; n++) {
                float p0 = __shfl_xor_sync(~0u, C[mt][n][0], 4);
                float p1 = __shfl_xor_sync(~0u, C[mt][n][1], 4);
                float p2 = __shfl_xor_sync(~0u, C[mt][n][2], 4);
                float p3 = __shfl_xor_sync(~0u, C[mt][n][3], 4);
                if ((g & 1) == 0) {
                    int m0 = mb + 32 * mg + 16 * mt + g;
                    int bi = m0 >> 11, nr = m0 & 2047;
                    int bhh = bi * HEADS + head;
                    size_t base = (size_t)(bhh * NT64 + (nr >> 6)) * (32 * 72);
                    int r2 = (nr & 63) >> 1;
                    int dw = 8 * (4 * ng + n) + 2 * q;
                    *(uint2*)&g_vp[base + (size_t)r2 * 72 + dw] =
                        make_uint2(pack2(C[mt][n][0], p0), pack2(C[mt][n][1], p1));
                    *(uint2*)&g_vp[base + (size_t)(r2 + 4) * 72 + dw] =
                        make_uint2(pack2(C[mt][n][2], p2), pack2(C[mt][n][3], p3));
                }
            }
    }
}

// ---------------- 3a) V per-tile column sums (parallel, 1024 blocks) ------
__global__ __launch_bounds__(128)
void vsuf_part() {
    int t  = blockIdx.x;            // tile 0..31
    int bh = blockIdx.y;
    int tid = threadIdx.x;
    int d = tid & 63, half = tid >> 6;
    const float* V = g_v + ((size_t)bh * NSEQ + t * 64 + half * 32) * DHEAD;
    float s = 0.f;
    #pragma unroll 8
    for (int r = 0; r < 32; r++)
        s += V[(size_t)r * DHEAD + d];
    __shared__ float red[128];
    red[tid] = s;
    __syncthreads();
    if (tid < 64)
        g_vpart[((size_t)bh * NT64 + t) * DHEAD + d] = red[tid] + red[tid + 64];
}

// ---------------- 3b) suffix scan (staged loads, register chain) ----------
__global__ __launch_bounds__(64)
void vsuf_scan() {
    int bh = blockIdx.x;
    int d  = threadIdx.x;
    float p[NT64];
    #pragma unroll
    for (int t = 0; t < NT64; t++)
        p[t] = g_vpart[((size_t)bh * NT64 + t) * DHEAD + d];
    float acc = 0.f;
    g_vsuf[((size_t)bh * (NT64 + 1) + NT64) * DHEAD + d] = 0.f;
    #pragma unroll
    for (int t = NT64 - 1; t >= 0; t--) {
        acc += p[t];
        g_vsuf[((size_t)bh * (NT64 + 1) + t) * DHEAD + d] = acc;
    }
}

// ---------------- 4) attention: cp.async images + fp16 mma ----------------
#define AQHI 0
#define AQLO 18432
#define ASTG 36864
#define STG_SZ 27648          /* KHI 9216 | KLO 9216 | VP 9216 */
#define ATTN_SMEM 92160

__global__ __launch_bounds__(256, 2)
void attn_kernel(float* __restrict__ out) {
    extern __shared__ char smc[];
    const uint32_t sb = smem_u32(smc);
    uint32_t* QHIw = (uint32_t*)(smc + AQHI);
    uint32_t* QLOw = (uint32_t*)(smc + AQLO);

    const int tid = threadIdx.x;
    const int w = tid >> 5, lane = tid & 31;
    const int g = lane >> 2, q = lane & 3;
    const int r0 = w * 16;
    const int qt = (NQT - 1) - blockIdx.x;     // big tiles first
    const int bh = blockIdx.y, b = bh >> 3, h = bh & 7;
    const int nkt = 2 * qt + 2;

    // Q images (hi+lo) + K/V tile 0 -> stage 0, one group
    {
        const char* qh = (const char*)&g_qih[(size_t)(bh * NQT + qt) * 4608];
        const char* ql = (const char*)&g_qil[(size_t)(bh * NQT + qt) * 4608];
        #pragma unroll
        for (int i = 0; i < 9; i++) {
            int c = tid + i * 256;
            if (c < 1152) CPA16(sb + AQHI + c * 16, qh + c * 16);
            else          CPA16(sb + AQLO + (c - 1152) * 16, ql + (c - 1152) * 16);
        }
        const char* kh = (const char*)&g_kih[(size_t)(bh * NT64 + 0) * 2304];
        const char* kl = (const char*)&g_kil[(size_t)(bh * NT64 + 0) * 2304];
        const char* vp = (const char*)&g_vp [(size_t)(bh * NT64 + 0) * 2304];
        #pragma unroll
        for (int i = 0; i < 7; i++) {
            int c = tid + i * 256;
            if (c < 576)       CPA16(sb + ASTG + c * 16, kh + c * 16);
            else if (c < 1152) CPA16(sb + ASTG + 9216 + (c - 576) * 16, kl + (c - 576) * 16);
            else if (c < 1728) CPA16(sb + ASTG + 18432 + (c - 1152) * 16, vp + (c - 1152) * 16);
        }
        CP_COMMIT();
    }

    float O[8][4];
    #pragma unroll
    for (int n = 0; n < 8; n++)
        #pragma unroll
        for (int j = 0; j < 4; j++) O[n][j] = 0.f;
    float ls0 = 0.f, ls1 = 0.f;
    float m0 = -1e30f, m1 = -1e30f;

    const int qrow0 = qt * 128 + r0 + g;
    const int qrow1 = qrow0 + 8;

    for (int kt = 0; kt < nkt; kt++) {
        CP_WAIT0();
        __syncthreads();
        // prefetch tile kt+1 into the other stage (overlaps compute below)
        if (kt + 1 < nkt) {
            uint32_t dst = sb + ASTG + ((kt + 1) & 1) * STG_SZ;
            const char* kh = (const char*)&g_kih[(size_t)(bh * NT64 + kt + 1) * 2304];
            const char* kl = (const char*)&g_kil[(size_t)(bh * NT64 + kt + 1) * 2304];
            const char* vp = (const char*)&g_vp [(size_t)(bh * NT64 + kt + 1) * 2304];
            #pragma unroll
            for (int i = 0; i < 7; i++) {
                int c = tid + i * 256;
                if (c < 576)       CPA16(dst + c * 16, kh + c * 16);
                else if (c < 1152) CPA16(dst + 9216 + (c - 576) * 16, kl + (c - 576) * 16);
                else if (c < 1728) CPA16(dst + 18432 + (c - 1152) * 16, vp + (c - 1152) * 16);
            }
            CP_COMMIT();
        }
        uint32_t* KHIw = (uint32_t*)(smc + ASTG + (kt & 1) * STG_SZ);
        uint32_t* KLOw = KHIw + 2304;
        uint32_t* VPw  = KHIw + 4608;

        // ---- S = Q K^T (16x64 per warp), 3-term fp16 split ----
        float S[8][4];
        #pragma unroll
        for (int n = 0; n < 8; n++)
            #pragma unroll
            for (int j = 0; j < 4; j++) S[n][j] = 0.f;
        #pragma unroll
        for (int ks = 0; ks < 4; ks++) {
            int a0w = (r0 + g) * 36 + 8 * ks + q;
            int a1w = (r0 + g + 8) * 36 + 8 * ks + q;
            uint32_t qh0 = QHIw[a0w],     qh1 = QHIw[a1w];
            uint32_t qh2 = QHIw[a0w + 4], qh3 = QHIw[a1w + 4];
            uint32_t ql0 = QLOw[a0w],     ql1 = QLOw[a1w];
            uint32_t ql2 = QLOw[a0w + 4], ql3 = QLOw[a1w + 4];
            #pragma unroll
            for (int n = 0; n < 8; n++) {
                int bw = (8 * n + g) * 36 + 8 * ks + q;
                uint32_t bh0 = KHIw[bw], bh1 = KHIw[bw + 4];
                uint32_t bl0 = KLOw[bw], bl1 = KLOw[bw + 4];
                mma16(S[n], qh0, qh1, qh2, qh3, bh0, bh1);
                mma16(S[n], qh0, qh1, qh2, qh3, bl0, bl1);
                mma16(S[n], ql0, ql1, ql2, ql3, bh0, bh1);
            }
        }

        // ---- mask (diagonal tiles only) ----
        if (kt >= 2 * qt) {
            #pragma unroll
            for (int n = 0; n < 8; n++) {
                int kc = kt * 64 + 8 * n + 2 * q;
                if (kc     > qrow0) S[n][0] = MASK_FILL;
                if (kc + 1 > qrow0) S[n][1] = MASK_FILL;
                if (kc     > qrow1) S[n][2] = MASK_FILL;
                if (kc + 1 > qrow1) S[n][3] = MASK_FILL;
            }
        }

        // ---- online max (coarse, per tile) ----
        float rm0 = -1e30f, rm1 = -1e30f;
        #pragma unroll
        for (int n = 0; n < 8; n++) {
            rm0 = fmaxf(rm0, fmaxf(S[n][0], S[n][1]));
            rm1 = fmaxf(rm1, fmaxf(S[n][2], S[n][3]));
        }
        rm0 = fmaxf(rm0, __shfl_xor_sync(~0u, rm0, 1));
        rm0 = fmaxf(rm0, __shfl_xor_sync(~0u, rm0, 2));
        rm1 = fmaxf(rm1, __shfl_xor_sync(~0u, rm1, 1));
        rm1 = fmaxf(rm1, __shfl_xor_sync(~0u, rm1, 2));
        float mn0 = fmaxf(m0, rm0), mn1 = fmaxf(m1, rm1);
        float sc0 = __expf(m0 - mn0), sc1 = __expf(m1 - mn1);
        m0 = mn0; m1 = mn1;
        ls0 *= sc0; ls1 *= sc1;
        #pragma unroll
        for (int n = 0; n < 8; n++) {
            O[n][0] *= sc0; O[n][1] *= sc0;
            O[n][2] *= sc1; O[n][3] *= sc1;
        }

        // ---- exp -> fp16 P (A-frags directly); l from rounded P ----
        uint32_t u01[8], u23[8];
        #pragma unroll
        for (int n = 0; n < 8; n++) {
            float p0 = __expf(S[n][0] - mn0), p1 = __expf(S[n][1] - mn0);
            float p2 = __expf(S[n][2] - mn1), p3 = __expf(S[n][3] - mn1);
            __half2 hp01 = __floats2half2_rn(p0, p1);
            __half2 hp23 = __floats2half2_rn(p2, p3);
            u01[n] = h2u(hp01); u23[n] = h2u(hp23);
            float2 f01 = __half22float2(hp01);
            float2 f23 = __half22float2(hp23);
            ls0 += f01.x + f01.y;
            ls1 += f23.x + f23.y;
        }

        // ---- O += P V ----
        #pragma unroll
        for (int kp = 0; kp < 4; kp++) {
            uint32_t a0 = u01[2*kp],     a1 = u23[2*kp];
            uint32_t a2 = u01[2*kp + 1], a3 = u23[2*kp + 1];
            #pragma unroll
            for (int n2 = 0; n2 < 8; n2++) {
                uint32_t b0 = VPw[(8*kp + q)     * 72 + 8*n2 + g];
                uint32_t b1 = VPw[(8*kp + q + 4) * 72 + 8*n2 + g];
                mma16(O[n2], a0, a1, a2, a3, b0, b1);
            }
        }
    }

    // ---- reduce l over quad, fold masked tail (rank-1), normalize, write --
    ls0 += __shfl_xor_sync(~0u, ls0, 1); ls0 += __shfl_xor_sync(~0u, ls0, 2);
    ls1 += __shfl_xor_sync(~0u, ls1, 1); ls1 += __shfl_xor_sync(~0u, ls1, 2);

    const float cntf = (float)(NSEQ - (qt + 1) * 128);
    const float e0 = __expf(MASK_FILL - m0);
    const float e1 = __expf(MASK_FILL - m1);
    const float inv0 = 1.0f / (ls0 + e0 * cntf);
    const float inv1 = 1.0f / (ls1 + e1 * cntf);
    const float* vs = &g_vsuf[((size_t)bh * (NT64 + 1) + (qt + 1) * 2) * DHEAD];

    #pragma unroll
    for (int n2 = 0; n2 < 8; n2++) {
        int col = 8 * n2 + 2 * q;
        float2 vv = *(const float2*)&vs[col];
        float o00 = (O[n2][0] + e0 * vv.x) * inv0;
        float o01 = (O[n2][1] + e0 * vv.y) * inv0;
        float o10 = (O[n2][2] + e1 * vv.x) * inv1;
        float o11 = (O[n2][3] + e1 * vv.y) * inv1;
        size_t ob0 = ((size_t)b * NSEQ + qrow0) * DIM + h * DHEAD + col;
        size_t ob1 = ((size_t)b * NSEQ + qrow1) * DIM + h * DHEAD + col;
        *(float2*)&out[ob0] = make_float2(o00, o01);
        *(float2*)&out[ob1] = make_float2(o10, o11);
    }
}

// ---------------- launch ----------------
extern "C" void kernel_launch(void* const* d_in, const int* in_sizes, int n_in,
                              void* d_out, int out_size) {
    const float* x     = (const float*)d_in[0];
    const float* gamma = (const float*)d_in[1];
    const float* beta  = (const float*)d_in[2];
    const float* w_qkv = (const float*)d_in[3];
    float* out = (float*)d_out;

    cudaFuncSetAttribute(qkv_gemm, cudaFuncAttributeMaxDynamicSharedMemorySize, GEMM_SMEM);
    cudaFuncSetAttribute(attn_kernel, cudaFuncAttributeMaxDynamicSharedMemorySize, ATTN_SMEM);

    ln_kernel<<<ROWS, 128>>>(x, gamma, beta);              // slot 1
    wconv_kernel<<<1536, 128>>>(w_qkv);                    // slot 2
    noop_kernel<<<1, 32>>>();                              // slot 3
    qkv_gemm<<<dim3(1536 / 64, ROWS / 128), 256, GEMM_SMEM>>>();  // slot 4 -> profiled
    vsuf_part<<<dim3(NT64, BH), 128>>>();
    vsuf_scan<<<BH, 64>>>();
    attn_kernel<<<dim3(NQT, BH), 256, ATTN_SMEM>>>(out);
}

// round 16
// speedup vs baseline: 1.0598x; 1.0598x over previous
#include <cuda_runtime.h>
#include <cuda_fp16.h>
#include <math.h>
#include <stdint.h>

#define BATCH 4
#define NSEQ 2048
#define DIM 512
#define HEADS 8
#define DHEAD 64
#define BH (BATCH*HEADS)      /* 32  */
#define ROWS (BATCH*NSEQ)     /* 8192 */
#define NT64 32               /* 64-row k tiles */
#define NQT 16                /* 128-row q tiles */
#define MASK_FILL 1e-8f

// ---------------- scratch ----------------
__device__ float g_hn [ROWS * DIM];
__device__ float g_v  [BH * NSEQ * DHEAD];          // fp32 V (vsuf)
__device__ float g_vpart[BH * NT64 * DHEAD];        // per-tile column sums
// MMA-ready fp16 images. Paired-word layout, 40-word row stride:
// word (8ks + 2q + h) holds the fragment half2 pair member h of (ks,q).
__device__ uint32_t g_qih[BH * NQT * 128 * 40];
__device__ uint32_t g_qil[BH * NQT * 128 * 40];
__device__ uint32_t g_kih[BH * NT64 * 64 * 40];
__device__ uint32_t g_kil[BH * NT64 * 64 * 40];
__device__ uint32_t g_vp [BH * NT64 * 32 * 72];

// ---------------- helpers ----------------
__device__ __forceinline__ void mma16(float* d, uint32_t a0, uint32_t a1,
                                      uint32_t a2, uint32_t a3,
                                      uint32_t b0, uint32_t b1) {
    asm volatile(
        "mma.sync.aligned.m16n8k16.row.col.f32.f16.f16.f32 "
        "{%0,%1,%2,%3}, {%4,%5,%6,%7}, {%8,%9}, {%0,%1,%2,%3};"
        : "+f"(d[0]), "+f"(d[1]), "+f"(d[2]), "+f"(d[3])
        : "r"(a0), "r"(a1), "r"(a2), "r"(a3), "r"(b0), "r"(b1));
}
__device__ __forceinline__ uint32_t h2u(__half2 h) {
    return *reinterpret_cast<uint32_t*>(&h);
}
__device__ __forceinline__ uint32_t pack2(float a, float b) {
    __half2 h = __floats2half2_rn(a, b);
    return h2u(h);
}
__device__ __forceinline__ void split2(float x, float y, uint32_t& hi, uint32_t& lo) {
    __half2 h = __floats2half2_rn(x, y);
    float2 back = __half22float2(h);
    hi = h2u(h);
    lo = pack2(x - back.x, y - back.y);
}
__device__ __forceinline__ uint32_t smem_u32(const void* p) {
    uint32_t a;
    asm("{ .reg .u64 t; cvta.to.shared.u64 t, %1; cvt.u32.u64 %0, t; }" : "=r"(a) : "l"(p));
    return a;
}
#define CPA16(dst, src) \
    asm volatile("cp.async.cg.shared.global [%0], [%1], 16;" :: "r"(dst), "l"(src) : "memory")
#define CP_COMMIT() asm volatile("cp.async.commit_group;" ::: "memory")
#define CP_WAIT0()  asm volatile("cp.async.wait_group 0;" ::: "memory")

// ---------------- 1) LayerNorm ----------------
__global__ __launch_bounds__(128)
void ln_kernel(const float* __restrict__ x,
               const float* __restrict__ gamma,
               const float* __restrict__ beta) {
    int row = blockIdx.x;
    int tid = threadIdx.x;
    const float4* xr = (const float4*)(x + (size_t)row * DIM);
    float4 v = xr[tid];
    float s  = v.x + v.y + v.z + v.w;
    float s2 = v.x*v.x + v.y*v.y + v.z*v.z + v.w*v.w;
    #pragma unroll
    for (int o = 16; o > 0; o >>= 1) {
        s  += __shfl_xor_sync(0xffffffffu, s,  o);
        s2 += __shfl_xor_sync(0xffffffffu, s2, o);
    }
    __shared__ float ss[4], ss2[4];
    int w = tid >> 5;
    if ((tid & 31) == 0) { ss[w] = s; ss2[w] = s2; }
    __syncthreads();
    s  = ss[0] + ss[1] + ss[2] + ss[3];
    s2 = ss2[0] + ss2[1] + ss2[2] + ss2[3];
    float mean = s * (1.0f / DIM);
    float var  = s2 * (1.0f / DIM) - mean * mean;
    float inv  = rsqrtf(var + 1e-5f);
    float4 g  = ((const float4*)gamma)[tid];
    float4 bt = ((const float4*)beta)[tid];
    float4 o;
    o.x = (v.x - mean) * inv * g.x + bt.x;
    o.y = (v.y - mean) * inv * g.y + bt.y;
    o.z = (v.z - mean) * inv * g.z + bt.z;
    o.w = (v.w - mean) * inv * g.w + bt.w;
    ((float4*)(g_hn + (size_t)row * DIM))[tid] = o;
}

// ---------------- 2) QKV GEMM: fp16 3-term split, 32x32 warp tiles --------
// (R14 structure; only the q/k image epilogue words move to paired layout)
#define GAHI 0
#define GALO 18432
#define GBHI 36864
#define GBLO 46080
#define GRAWA 55296
#define GRAWB 88064
#define GEMM_SMEM 104448
__global__ __launch_bounds__(256, 2)
void qkv_gemm(const float* __restrict__ W) {
    extern __shared__ char smc[];
    uint32_t* AHIw = (uint32_t*)(smc + GAHI);
    uint32_t* ALOw = (uint32_t*)(smc + GALO);
    uint32_t* BHIw = (uint32_t*)(smc + GBHI);
    uint32_t* BLOw = (uint32_t*)(smc + GBLO);
    const float4* rawA = (const float4*)(smc + GRAWA);   // [128][16]
    const float4* rawB = (const float4*)(smc + GRAWB);   // [64][16]
    const uint32_t sb = smem_u32(smc);
    const int nb = blockIdx.x * 64;
    const int mb = blockIdx.y * 128;
    const int tid = threadIdx.x;
    const int w = tid >> 5, lane = tid & 31;
    const int g = lane >> 2, q = lane & 3;
    const int mg = w & 3;          // m-group: rows 32*mg..+31
    const int ng = w >> 2;         // n-group: cols 32*ng..+31

    float C[2][4][4];
    #pragma unroll
    for (int mt = 0; mt < 2; mt++)
        #pragma unroll
        for (int n = 0; n < 4; n++)
            #pragma unroll
            for (int j = 0; j < 4; j++) C[mt][n][j] = 0.f;

    // prefetch chunk 0
    #pragma unroll
    for (int i = 0; i < 12; i++) {
        int c = tid + i * 256;
        if (c < 2048) {
            CPA16(sb + GRAWA + c * 16,
                  &g_hn[(size_t)(mb + (c >> 4)) * DIM + ((c & 15) << 2)]);
        } else {
            int c2 = c - 2048;
            CPA16(sb + GRAWB + c2 * 16,
                  &W[(size_t)(nb + (c2 >> 4)) * DIM + ((c2 & 15) << 2)]);
        }
    }
    CP_COMMIT();

    for (int ch = 0; ch < 8; ch++) {
        CP_WAIT0();
        __syncthreads();
        // convert raw -> fp16 split bufs
        #pragma unroll
        for (int i = 0; i < 8; i++) {
            int idx = tid + i * 256;
            int row = idx >> 4, cf = idx & 15;
            float4 v = rawA[row * 16 + cf];
            uint32_t h0, l0, h1, l1;
            split2(v.x, v.y, h0, l0); split2(v.z, v.w, h1, l1);
            *(uint2*)(AHIw + row * 36 + 2 * cf) = make_uint2(h0, h1);
            *(uint2*)(ALOw + row * 36 + 2 * cf) = make_uint2(l0, l1);
        }
        #pragma unroll
        for (int i = 0; i < 4; i++) {
            int idx = tid + i * 256;
            int row = idx >> 4, cf = idx & 15;
            float4 v = rawB[row * 16 + cf];
            uint32_t h0, l0, h1, l1;
            split2(v.x, v.y, h0, l0); split2(v.z, v.w, h1, l1);
            *(uint2*)(BHIw + row * 36 + 2 * cf) = make_uint2(h0, h1);
            *(uint2*)(BLOw + row * 36 + 2 * cf) = make_uint2(l0, l1);
        }
        __syncthreads();
        // prefetch chunk ch+1 (overlaps with compute below)
        if (ch + 1 < 8) {
            const int k0 = (ch + 1) * 64;
            #pragma unroll
            for (int i = 0; i < 12; i++) {
                int c = tid + i * 256;
                if (c < 2048) {
                    CPA16(sb + GRAWA + c * 16,
                          &g_hn[(size_t)(mb + (c >> 4)) * DIM + k0 + ((c & 15) << 2)]);
                } else {
                    int c2 = c - 2048;
                    CPA16(sb + GRAWB + c2 * 16,
                          &W[(size_t)(nb + (c2 >> 4)) * DIM + k0 + ((c2 & 15) << 2)]);
                }
            }
            CP_COMMIT();
        }
        // compute: 2 m-tiles x 4 n-tiles per warp
        #pragma unroll
        for (int ks = 0; ks < 4; ks++) {
            uint32_t ah[2][4], al[2][4];
            #pragma unroll
            for (int mt = 0; mt < 2; mt++) {
                int a0w = (32 * mg + 16 * mt + g) * 36 + 8 * ks + q;
                int a1w = a0w + 8 * 36;
                ah[mt][0] = AHIw[a0w];     ah[mt][1] = AHIw[a1w];
                ah[mt][2] = AHIw[a0w + 4]; ah[mt][3] = AHIw[a1w + 4];
                al[mt][0] = ALOw[a0w];     al[mt][1] = ALOw[a1w];
                al[mt][2] = ALOw[a0w + 4]; al[mt][3] = ALOw[a1w + 4];
            }
            #pragma unroll
            for (int n = 0; n < 4; n++) {
                int bw = (32 * ng + 8 * n + g) * 36 + 8 * ks + q;
                uint32_t bh0 = BHIw[bw], bh1 = BHIw[bw + 4];
                uint32_t bl0 = BLOw[bw], bl1 = BLOw[bw + 4];
                #pragma unroll
                for (int mt = 0; mt < 2; mt++) {
                    mma16(C[mt][n], ah[mt][0], ah[mt][1], ah[mt][2], ah[mt][3], bh0, bh1);
                    mma16(C[mt][n], ah[mt][0], ah[mt][1], ah[mt][2], ah[mt][3], bl0, bl1);
                    mma16(C[mt][n], al[mt][0], al[mt][1], al[mt][2], al[mt][3], bh0, bh1);
                }
            }
        }
    }

    // ---- epilogue: emit paired-layout images (q,k) / fp32 + VP (v) ----
    const int chunk = nb / 512;            // 0=q 1=k 2=v
    const int head  = (nb % 512) >> 6;
    if (chunk == 0) {
        #pragma unroll
        for (int mt = 0; mt < 2; mt++)
            #pragma unroll
            for (int n = 0; n < 4; n++) {
                int na = 4 * ng + n;
                int wrd = 8 * (na >> 1) + 2 * q + (na & 1);
                #pragma unroll
                for (int rr = 0; rr < 2; rr++) {
                    int m  = mb + 32 * mg + 16 * mt + g + rr * 8;
                    int bi = m >> 11, nr = m & 2047;
                    int bhh = bi * HEADS + head;
                    size_t idx = ((size_t)(bhh * NQT + (nr >> 7)) * 128 + (nr & 127)) * 40 + wrd;
                    uint32_t hi, lo;
                    split2(C[mt][n][rr * 2], C[mt][n][rr * 2 + 1], hi, lo);
                    g_qih[idx] = hi; g_qil[idx] = lo;
                }
            }
    } else if (chunk == 1) {
        #pragma unroll
        for (int mt = 0; mt < 2; mt++)
            #pragma unroll
            for (int n = 0; n < 4; n++) {
                int na = 4 * ng + n;
                int wrd = 8 * (na >> 1) + 2 * q + (na & 1);
                #pragma unroll
                for (int rr = 0; rr < 2; rr++) {
                    int m  = mb + 32 * mg + 16 * mt + g + rr * 8;
                    int bi = m >> 11, nr = m & 2047;
                    int bhh = bi * HEADS + head;
                    size_t idx = ((size_t)(bhh * NT64 + (nr >> 6)) * 64 + (nr & 63)) * 40 + wrd;
                    uint32_t hi, lo;
                    split2(C[mt][n][rr * 2], C[mt][n][rr * 2 + 1], hi, lo);
                    g_kih[idx] = hi; g_kil[idx] = lo;
                }
            }
    } else {
        // fp32 V for vsuf
        #pragma unroll
        for (int mt = 0; mt < 2; mt++)
            #pragma unroll
            for (int n = 0; n < 4; n++) {
                int col = 8 * (4 * ng + n) + 2 * q;
                #pragma unroll
                for (int rr = 0; rr < 2; rr++) {
                    int m  = mb + 32 * mg + 16 * mt + g + rr * 8;
                    int bi = m >> 11, nr = m & 2047;
                    size_t ob = (((size_t)(bi * HEADS + head)) * NSEQ + nr) * DHEAD + col;
                    *(float2*)&g_v[ob] = make_float2(C[mt][n][rr * 2], C[mt][n][rr * 2 + 1]);
                }
            }
        // VP image: half2 word [r2][d] = (V[2r2][d], V[2r2+1][d]); even-g lanes
        #pragma unroll
        for (int mt = 0; mt < 2; mt++)
            #pragma unroll
            for (int n = 0; n < 4; n++) {
                float p0 = __shfl_xor_sync(~0u, C[mt][n][0], 4);
                float p1 = __shfl_xor_sync(~0u, C[mt][n][1], 4);
                float p2 = __shfl_xor_sync(~0u, C[mt][n][2], 4);
                float p3 = __shfl_xor_sync(~0u, C[mt][n][3], 4);
                if ((g & 1) == 0) {
                    int m0 = mb + 32 * mg + 16 * mt + g;
                    int bi = m0 >> 11, nr = m0 & 2047;
                    int bhh = bi * HEADS + head;
                    size_t base = (size_t)(bhh * NT64 + (nr >> 6)) * (32 * 72);
                    int r2 = (nr & 63) >> 1;
                    int dw = 8 * (4 * ng + n) + 2 * q;
                    *(uint2*)&g_vp[base + (size_t)r2 * 72 + dw] =
                        make_uint2(pack2(C[mt][n][0], p0), pack2(C[mt][n][1], p1));
                    *(uint2*)&g_vp[base + (size_t)(r2 + 4) * 72 + dw] =
                        make_uint2(pack2(C[mt][n][2], p2), pack2(C[mt][n][3], p3));
                }
            }
    }
}

// ---------------- 3) V per-tile column sums (parallel, 1024 blocks) ------
__global__ __launch_bounds__(128)
void vsuf_part() {
    int t  = blockIdx.x;            // tile 0..31
    int bh = blockIdx.y;
    int tid = threadIdx.x;
    int d = tid & 63, half = tid >> 6;
    const float* V = g_v + ((size_t)bh * NSEQ + t * 64 + half * 32) * DHEAD;
    float s = 0.f;
    #pragma unroll 8
    for (int r = 0; r < 32; r++)
        s += V[(size_t)r * DHEAD + d];
    __shared__ float red[128];
    red[tid] = s;
    __syncthreads();
    if (tid < 64)
        g_vpart[((size_t)bh * NT64 + t) * DHEAD + d] = red[tid] + red[tid + 64];
}

// ---------------- 4) attention: paired images, LDS.64 frags --------------
#define AQHI 0
#define AQLO 20480
#define ASTG 40960
#define STG_SZ 29696          /* KHI 10240 | KLO 10240 | VP 9216 */
#define ATTN_SMEM 100352

__global__ __launch_bounds__(256, 2)
void attn_kernel(float* __restrict__ out) {
    extern __shared__ char smc[];
    __shared__ float vsm[64];
    const uint32_t sb = smem_u32(smc);
    uint32_t* QHIw = (uint32_t*)(smc + AQHI);
    uint32_t* QLOw = (uint32_t*)(smc + AQLO);

    const int tid = threadIdx.x;
    const int w = tid >> 5, lane = tid & 31;
    const int g = lane >> 2, q = lane & 3;
    const int r0 = w * 16;
    const int qt = (NQT - 1) - blockIdx.x;     // big tiles first
    const int bh = blockIdx.y, b = bh >> 3, h = bh & 7;
    const int nkt = 2 * qt + 2;

    // Q images (hi+lo, 2*20480B) + K/V tile 0 -> stage 0, one group
    {
        const char* qh = (const char*)&g_qih[(size_t)(bh * NQT + qt) * 5120];
        const char* ql = (const char*)&g_qil[(size_t)(bh * NQT + qt) * 5120];
        #pragma unroll
        for (int i = 0; i < 10; i++) {
            int c = tid + i * 256;
            if (c < 1280) CPA16(sb + AQHI + c * 16, qh + c * 16);
            else          CPA16(sb + AQLO + (c - 1280) * 16, ql + (c - 1280) * 16);
        }
        const char* kh = (const char*)&g_kih[(size_t)(bh * NT64 + 0) * 2560];
        const char* kl = (const char*)&g_kil[(size_t)(bh * NT64 + 0) * 2560];
        const char* vp = (const char*)&g_vp [(size_t)(bh * NT64 + 0) * 2304];
        #pragma unroll
        for (int i = 0; i < 8; i++) {
            int c = tid + i * 256;
            if (c < 640)       CPA16(sb + ASTG + c * 16, kh + c * 16);
            else if (c < 1280) CPA16(sb + ASTG + 10240 + (c - 640) * 16, kl + (c - 640) * 16);
            else if (c < 1856) CPA16(sb + ASTG + 20480 + (c - 1280) * 16, vp + (c - 1280) * 16);
        }
        CP_COMMIT();
    }

    // masked-tail V column sum for this q-tile (tiles > 2qt+1)
    if (tid < 64) {
        float acc = 0.f;
        for (int t = 2 * qt + 2; t < NT64; t++)
            acc += g_vpart[((size_t)bh * NT64 + t) * DHEAD + tid];
        vsm[tid] = acc;
    }

    float O[8][4];
    #pragma unroll
    for (int n = 0; n < 8; n++)
        #pragma unroll
        for (int j = 0; j < 4; j++) O[n][j] = 0.f;
    float ls0 = 0.f, ls1 = 0.f;
    float m0 = -1e30f, m1 = -1e30f;

    const int qrow0 = qt * 128 + r0 + g;
    const int qrow1 = qrow0 + 8;

    for (int kt = 0; kt < nkt; kt++) {
        CP_WAIT0();
        __syncthreads();
        // prefetch tile kt+1 into the other stage (overlaps compute below)
        if (kt + 1 < nkt) {
            uint32_t dst = sb + ASTG + ((kt + 1) & 1) * STG_SZ;
            const char* kh = (const char*)&g_kih[(size_t)(bh * NT64 + kt + 1) * 2560];
            const char* kl = (const char*)&g_kil[(size_t)(bh * NT64 + kt + 1) * 2560];
            const char* vp = (const char*)&g_vp [(size_t)(bh * NT64 + kt + 1) * 2304];
            #pragma unroll
            for (int i = 0; i < 8; i++) {
                int c = tid + i * 256;
                if (c < 640)       CPA16(dst + c * 16, kh + c * 16);
                else if (c < 1280) CPA16(dst + 10240 + (c - 640) * 16, kl + (c - 640) * 16);
                else if (c < 1856) CPA16(dst + 20480 + (c - 1280) * 16, vp + (c - 1280) * 16);
            }
            CP_COMMIT();
        }
        uint32_t* KHIw = (uint32_t*)(smc + ASTG + (kt & 1) * STG_SZ);
        uint32_t* KLOw = KHIw + 2560;
        uint32_t* VPw  = KHIw + 5120;

        // ---- S = Q K^T (16x64 per warp), 3-term fp16 split; LDS.64 frags --
        float S[8][4];
        #pragma unroll
        for (int n = 0; n < 8; n++)
            #pragma unroll
            for (int j = 0; j < 4; j++) S[n][j] = 0.f;
        #pragma unroll
        for (int ks = 0; ks < 4; ks++) {
            int aw = (r0 + g) * 40 + 8 * ks + 2 * q;
            uint2 qa = *(const uint2*)&QHIw[aw];
            uint2 qb = *(const uint2*)&QHIw[aw + 320];
            uint2 la = *(const uint2*)&QLOw[aw];
            uint2 lb = *(const uint2*)&QLOw[aw + 320];
            #pragma unroll
            for (int n = 0; n < 8; n++) {
                int bw = (8 * n + g) * 40 + 8 * ks + 2 * q;
                uint2 kh = *(const uint2*)&KHIw[bw];
                uint2 kl = *(const uint2*)&KLOw[bw];
                mma16(S[n], qa.x, qb.x, qa.y, qb.y, kh.x, kh.y);
                mma16(S[n], qa.x, qb.x, qa.y, qb.y, kl.x, kl.y);
                mma16(S[n], la.x, lb.x, la.y, lb.y, kh.x, kh.y);
            }
        }

        // ---- mask (diagonal tiles only) ----
        if (kt >= 2 * qt) {
            #pragma unroll
            for (int n = 0; n < 8; n++) {
                int kc = kt * 64 + 8 * n + 2 * q;
                if (kc     > qrow0) S[n][0] = MASK_FILL;
                if (kc + 1 > qrow0) S[n][1] = MASK_FILL;
                if (kc     > qrow1) S[n][2] = MASK_FILL;
                if (kc + 1 > qrow1) S[n][3] = MASK_FILL;
            }
        }

        // ---- online max (coarse, per tile) ----
        float rm0 = -1e30f, rm1 = -1e30f;
        #pragma unroll
        for (int n = 0; n < 8; n++) {
            rm0 = fmaxf(rm0, fmaxf(S[n][0], S[n][1]));
            rm1 = fmaxf(rm1, fmaxf(S[n][2], S[n][3]));
        }
        rm0 = fmaxf(rm0, __shfl_xor_sync(~0u, rm0, 1));
        rm0 = fmaxf(rm0, __shfl_xor_sync(~0u, rm0, 2));
        rm1 = fmaxf(rm1, __shfl_xor_sync(~0u, rm1, 1));
        rm1 = fmaxf(rm1, __shfl_xor_sync(~0u, rm1, 2));
        float mn0 = fmaxf(m0, rm0), mn1 = fmaxf(m1, rm1);
        float sc0 = __expf(m0 - mn0), sc1 = __expf(m1 - mn1);
        m0 = mn0; m1 = mn1;
        ls0 *= sc0; ls1 *= sc1;
        #pragma unroll
        for (int n = 0; n < 8; n++) {
            O[n][0] *= sc0; O[n][1] *= sc0;
            O[n][2] *= sc1; O[n][3] *= sc1;
        }

        // ---- exp -> fp16 P (A-frags directly); l from rounded P ----
        uint32_t u01[8], u23[8];
        #pragma unroll
        for (int n = 0; n < 8; n++) {
            float p0 = __expf(S[n][0] - mn0), p1 = __expf(S[n][1] - mn0);
            float p2 = __expf(S[n][2] - mn1), p3 = __expf(S[n][3] - mn1);
            __half2 hp01 = __floats2half2_rn(p0, p1);
            __half2 hp23 = __floats2half2_rn(p2, p3);
            u01[n] = h2u(hp01); u23[n] = h2u(hp23);
            float2 f01 = __half22float2(hp01);
            float2 f23 = __half22float2(hp23);
            ls0 += f01.x + f01.y;
            ls1 += f23.x + f23.y;
        }

        // ---- O += P V ----
        #pragma unroll
        for (int kp = 0; kp < 4; kp++) {
            uint32_t a0 = u01[2*kp],     a1 = u23[2*kp];
            uint32_t a2 = u01[2*kp + 1], a3 = u23[2*kp + 1];
            #pragma unroll
            for (int n2 = 0; n2 < 8; n2++) {
                uint32_t b0 = VPw[(8*kp + q)     * 72 + 8*n2 + g];
                uint32_t b1 = VPw[(8*kp + q + 4) * 72 + 8*n2 + g];
                mma16(O[n2], a0, a1, a2, a3, b0, b1);
            }
        }
    }

    // ---- reduce l over quad, fold masked tail (rank-1), normalize, write --
    ls0 += __shfl_xor_sync(~0u, ls0, 1); ls0 += __shfl_xor_sync(~0u, ls0, 2);
    ls1 += __shfl_xor_sync(~0u, ls1, 1); ls1 += __shfl_xor_sync(~0u, ls1, 2);

    const float cntf = (float)(NSEQ - (qt + 1) * 128);
    const float e0 = __expf(MASK_FILL - m0);
    const float e1 = __expf(MASK_FILL - m1);
    const float inv0 = 1.0f / (ls0 + e0 * cntf);
    const float inv1 = 1.0f / (ls1 + e1 * cntf);

    #pragma unroll
    for (int n2 = 0; n2 < 8; n2++) {
        int col = 8 * n2 + 2 * q;
        float vx = vsm[col], vy = vsm[col + 1];
        float o00 = (O[n2][0] + e0 * vx) * inv0;
        float o01 = (O[n2][1] + e0 * vy) * inv0;
        float o10 = (O[n2][2] + e1 * vx) * inv1;
        float o11 = (O[n2][3] + e1 * vy) * inv1;
        size_t ob0 = ((size_t)b * NSEQ + qrow0) * DIM + h * DHEAD + col;
        size_t ob1 = ((size_t)b * NSEQ + qrow1) * DIM + h * DHEAD + col;
        *(float2*)&out[ob0] = make_float2(o00, o01);
        *(float2*)&out[ob1] = make_float2(o10, o11);
    }
}

// ---------------- launch ----------------
extern "C" void kernel_launch(void* const* d_in, const int* in_sizes, int n_in,
                              void* d_out, int out_size) {
    const float* x     = (const float*)d_in[0];
    const float* gamma = (const float*)d_in[1];
    const float* beta  = (const float*)d_in[2];
    const float* w_qkv = (const float*)d_in[3];
    float* out = (float*)d_out;

    cudaFuncSetAttribute(qkv_gemm, cudaFuncAttributeMaxDynamicSharedMemorySize, GEMM_SMEM);
    cudaFuncSetAttribute(attn_kernel, cudaFuncAttributeMaxDynamicSharedMemorySize, ATTN_SMEM);

    ln_kernel<<<ROWS, 128>>>(x, gamma, beta);                               // slot 1
    qkv_gemm<<<dim3(1536 / 64, ROWS / 128), 256, GEMM_SMEM>>>(w_qkv);       // slot 2
    vsuf_part<<<dim3(NT64, BH), 128>>>();                                   // slot 3
    attn_kernel<<<dim3(NQT, BH), 256, ATTN_SMEM>>>(out);                    // slot 4 -> profiled
}